// round 15
// baseline (speedup 1.0000x reference)
#include <cuda_runtime.h>
#include <cuda_fp16.h>
#include <cstdint>

// ---------------- problem constants ----------------
#define B_DIM 128
#define H_DIM 101            // 100 hidden + leading 1
#define AV 10201             // 101*101
#define AVP 10208            // padded (even) row stride for fp16 VT copies
#define F_DIM 1030301        // 101^3
#define P_DIM 300
#define KT 64                // K per pipeline tile
#define TILES 16099          // ceil(F_DIM / 64)
#define NCTA 148             // K-split
#define NTHR 512
#define A_BYTES (128 * 128)           // A tile: 128 rows x 128B (fp16, k64)
#define B_BYTES (320 * 256)           // B tile: 320 rows x 256B (fp32; rows>=300 junk)
#define STG_BYTES (A_BYTES + B_BYTES) // 98304
#define DYN_SMEM (2 * STG_BYTES)      // 196608
#define RPARTS 8

// ---------------- device scratch (no allocs allowed) ----------------
__device__ float g_HA[B_DIM * H_DIM];                            // audio hidden (with leading 1)
__device__ float g_VT[B_DIM * AV];                               // fp32 VT (slow path)
__device__ __half g_VTh0[B_DIM * AVP];                           // fp16 VT, even alignment
__device__ __half g_VTh1[B_DIM * AVP];                           // fp16 VT shifted by 1
__device__ __align__(16) float g_part[(size_t)NCTA * B_DIM * P_DIM];
__device__ __align__(16) float g_R4[RPARTS * B_DIM * P_DIM];
__device__ __align__(16) float g_H[B_DIM * P_DIM];

// ---------------- helpers ----------------
__device__ __forceinline__ uint32_t smem_u32(const void* p) {
    uint32_t a;
    asm("{ .reg .u64 t; cvta.to.shared.u64 t, %1; cvt.u32.u64 %0, t; }" : "=r"(a) : "l"(p));
    return a;
}
// pack two fp32 -> f16x2 (first arg -> upper half, second -> lower half)
__device__ __forceinline__ uint32_t cvt2h(float hi, float lo) {
    uint32_t r;
    asm("cvt.rn.f16x2.f32 %0, %1, %2;" : "=r"(r) : "f"(hi), "f"(lo));
    return r;
}
__device__ __forceinline__ void sts64(uint32_t a, uint32_t v0, uint32_t v1) {
    asm volatile("st.shared.v2.b32 [%0], {%1,%2};" :: "r"(a), "r"(v0), "r"(v1) : "memory");
}
__device__ __forceinline__ void lds64(uint32_t a, uint32_t& v0, uint32_t& v1) {
    asm volatile("ld.shared.v2.b32 {%0,%1}, [%2];" : "=r"(v0), "=r"(v1) : "r"(a));
}
__device__ __forceinline__ void lds128(uint32_t a, uint32_t& v0, uint32_t& v1,
                                       uint32_t& v2, uint32_t& v3) {
    asm volatile("ld.shared.v4.b32 {%0,%1,%2,%3}, [%4];"
                 : "=r"(v0), "=r"(v1), "=r"(v2), "=r"(v3) : "r"(a));
}
__device__ __forceinline__ void cpasync4(uint32_t dst, const void* src) {
    asm volatile("cp.async.ca.shared.global [%0], [%1], 4;" :: "r"(dst), "l"(src) : "memory");
}
__device__ __forceinline__ void cp_commit() {
    asm volatile("cp.async.commit_group;" ::: "memory");
}
__device__ __forceinline__ void cp_wait0() {
    asm volatile("cp.async.wait_group 0;" ::: "memory");
}
// fp16 MMA, m16n8k16, fp32 accumulate
__device__ __forceinline__ void mma_f16(float& d0, float& d1, float& d2, float& d3,
                                        uint32_t a0, uint32_t a1, uint32_t a2, uint32_t a3,
                                        uint32_t b0, uint32_t b1) {
    asm volatile("mma.sync.aligned.m16n8k16.row.col.f32.f16.f16.f32 "
                 "{%0,%1,%2,%3}, {%4,%5,%6,%7}, {%8,%9}, {%0,%1,%2,%3};"
                 : "+f"(d0), "+f"(d1), "+f"(d2), "+f"(d3)
                 : "r"(a0), "r"(a1), "r"(a2), "r"(a3), "r"(b0), "r"(b1));
}

// ---------------- kernel 1: fused encoders + VT precompute ----------------
// Block b: compute HA/HV/HT for batch b, then VT = hv (x) ht in fp32 + two fp16 copies.
__global__ void prep_kernel(const float* __restrict__ ax, const float* __restrict__ vx,
                            const float* __restrict__ tx,
                            const float* __restrict__ Wa, const float* __restrict__ ba,
                            const float* __restrict__ Wv, const float* __restrict__ bv,
                            const float* __restrict__ Wt, const float* __restrict__ bt) {
    __shared__ float xs[900];
    __shared__ float hv[H_DIM], ht[H_DIM];
    int b = blockIdx.x;
    int tid = threadIdx.x;   // 384 threads
    for (int i = tid; i < 900; i += 384) {
        const float* x = (i < 300) ? ax : (i < 600) ? vx : tx;
        xs[i] = x[b * 300 + (i % 300)];
    }
    __syncthreads();
    if (tid < 300) {
        int m = tid / 100, jj = tid - m * 100;
        const float* W    = (m == 0) ? Wa : (m == 1) ? Wv : Wt;
        const float* bias = (m == 0) ? ba : (m == 1) ? bv : bt;
        const float* w = W + jj * 300;
        const float* xp = xs + m * 300;
        float s = 0.0f;
        #pragma unroll 4
        for (int p = 0; p < 300; p++) s += xp[p] * __ldg(w + p);
        s += __ldg(bias + jj);
        if (m == 0) g_HA[b * H_DIM + 1 + jj] = s;
        else if (m == 1) hv[1 + jj] = s;
        else ht[1 + jj] = s;
    }
    if (tid == 300) g_HA[b * H_DIM] = 1.0f;
    if (tid == 301) hv[0] = 1.0f;
    if (tid == 302) ht[0] = 1.0f;
    __syncthreads();
    for (int i = tid; i < AV; i += 384) {
        int v = i / 101, t = i - v * 101;
        float f = hv[v] * ht[t];
        g_VT[b * AV + i] = f;
        __half h = __float2half(f);
        g_VTh0[(size_t)b * AVP + i] = h;
        if (i) g_VTh1[(size_t)b * AVP + i - 1] = h;
    }
}

// ---------------- dummy kernels: keep main_kernel as launch #4 for the ncu window ----------------
__global__ void dummy_kernel() {}

// ---------------- accumulator flush: scale rows by ha (or 1) and add into g_part ----------------
__device__ __forceinline__ void flush_acc(float (&acc)[4][5][4], float* dst,
                                          int wm, int wn, int lr, int lc,
                                          int a_idx /* -1 => scale 1 */, bool add) {
    #pragma unroll
    for (int m = 0; m < 4; m++) {
        int row = wm * 64 + m * 16 + lr;
        float s0 = 1.0f, s1 = 1.0f;
        if (a_idx >= 0) {
            s0 = g_HA[row * H_DIM + a_idx];
            s1 = g_HA[(row + 8) * H_DIM + a_idx];
        }
        #pragma unroll
        for (int n = 0; n < 5; n++) {
            int col = wn * 40 + n * 8 + lc * 2;
            if (col < 300) {
                float* p0 = dst + (size_t)row * P_DIM + col;
                float* p1 = dst + (size_t)(row + 8) * P_DIM + col;
                float2 v0 = make_float2(acc[m][n][0] * s0, acc[m][n][1] * s0);
                float2 v1 = make_float2(acc[m][n][2] * s1, acc[m][n][3] * s1);
                if (add) {
                    float2 o0 = *reinterpret_cast<float2*>(p0);
                    float2 o1 = *reinterpret_cast<float2*>(p1);
                    v0.x += o0.x; v0.y += o0.y; v1.x += o1.x; v1.y += o1.y;
                }
                *reinterpret_cast<float2*>(p0) = v0;
                *reinterpret_cast<float2*>(p1) = v1;
            }
        }
    }
    #pragma unroll
    for (int m = 0; m < 4; m++)
        #pragma unroll
        for (int n = 0; n < 5; n++)
            #pragma unroll
            for (int e = 0; e < 4; e++) acc[m][n][e] = 0.0f;
}

// ---------------- kernel 2: main split-K GEMM (512 thr, fp16 m16n8k16, KT=64) ----------------
// acc holds raw VT @ W1^T; per-CTA 'a' spans <=2 values, so ha scaling happens at
// <=3 flush points (pure-a0 segment, premultiplied mixed tile, pure-a1 segment).
// A smem: fp16, row 128B, k-contiguous, 8B granule gi -> gi ^ (8*(row&1)). Fast path
// fills it with 8 cp.async of the precomputed fp16 VT (parity-selected copy).
// B smem: fp32, row 256B, k contiguous, 16B chunk ^ ((row&1)*4) (proven layout).
// Slot<->phys-k bijection identical on A and B -> exact contraction.
__global__ void __launch_bounds__(NTHR, 1) main_kernel(const float* __restrict__ W1) {
    extern __shared__ char dyn[];
    uint32_t base_s = smem_u32(dyn);

    int tid = threadIdx.x, wid = tid >> 5, lane = tid & 31;
    int cta = blockIdx.x;
    int wm = wid & 1;          // M half: rows wm*64
    int wn = wid >> 1;         // N block: cols wn*40 (0..7)
    int lr = lane >> 2;        // 0..7
    int lc = lane & 3;         // 0..3

    // contiguous K-tile range for this CTA
    int q = TILES / NCTA;                  // 108
    int r = TILES - q * NCTA;              // 115
    int t0 = cta * q + min(cta, r);
    int nt = q + (cta < r ? 1 : 0);

    // ---- producer rolling state ----
    int kp = t0 * KT;
    int ap = kp / AV;
    int vp = kp - ap * AV;

    // segment bookkeeping (captured BEFORE producer advances)
    int a0 = ap;
    int W0 = AV - vp;
    int cf = W0 / KT;                      // tiles fully inside a0
    bool mixed = (W0 % KT) != 0;
    bool hasb = (cf < nt);

    // A producer mapping: row = tid>>2, q-chunk = tid&3 (32B of the 128B row)
    int arow = tid >> 2;
    int aq   = tid & 3;
    uint32_t asw = 8u * (uint32_t)(arow & 1);
    // B producer mapping: warp w covers rows bn0+16i; thread covers words bw0, bw0+32
    int bn0 = tid >> 5;
    int bw0 = tid & 31;
    const float* Wrow = W1 + (size_t)bn0 * F_DIM;
    uint32_t bdst0 = (uint32_t)(bn0 * 256 + (((bw0 >> 2) ^ ((bn0 & 1) * 4)) * 16) + (bw0 & 3) * 4);

    float acc[4][5][4];
    #pragma unroll
    for (int m = 0; m < 4; m++)
        #pragma unroll
        for (int n = 0; n < 5; n++)
            #pragma unroll
            for (int e = 0; e < 4; e++) acc[m][n][e] = 0.0f;

#define PRODUCE(S) do {                                                               \
    uint32_t aB = base_s + (S) * STG_BYTES;                                           \
    uint32_t bB = aB + A_BYTES;                                                       \
    /* ---- A tile ---- */                                                            \
    if (vp <= AV - KT && kp + KT <= F_DIM) {  /* pure tile: raw fp16 VT via cp.async */\
        const __half* vbp = (ap & 1) ? g_VTh1 : g_VTh0;                               \
        const char* asrc = (const char*)(vbp + (size_t)arow * AVP + (vp - (ap & 1)))  \
                           + 32 * aq;                                                 \
        uint32_t ad = aB + arow * 128;                                                \
        _Pragma("unroll")                                                             \
        for (int j = 0; j < 8; j++) {                                                 \
            uint32_t gi = (uint32_t)(4 * aq + (j >> 1)) ^ asw;                        \
            cpasync4(ad + gi * 8 + (j & 1) * 4, asrc + 4 * j);                        \
        }                                                                             \
    } else {                                  /* mixed/tail: premultiplied slow path */\
        _Pragma("unroll")                                                             \
        for (int u = 0; u < 4; u++) {                                                 \
            float f[4];                                                               \
            _Pragma("unroll")                                                         \
            for (int e = 0; e < 4; e++) {                                             \
                int off = 16 * aq + 4 * u + e;                                        \
                int k = kp + off;                                                     \
                float val = 0.0f;                                                     \
                if (k < F_DIM) {                                                      \
                    int vv = vp + off;                                                \
                    int wrap = (vv >= AV);                                            \
                    int a = ap + wrap;                                                \
                    int vt = vv - (wrap ? AV : 0);                                    \
                    val = g_HA[arow * H_DIM + a] * g_VT[(size_t)arow * AV + vt];      \
                }                                                                     \
                f[e] = val;                                                           \
            }                                                                         \
            uint32_t gi = (uint32_t)(4 * aq + u) ^ asw;                               \
            sts64(aB + arow * 128 + gi * 8, cvt2h(f[1], f[0]), cvt2h(f[3], f[2]));    \
        }                                                                             \
    }                                                                                 \
    /* ---- B tile: 300 rows x 64 words (fp32), rolling pointers ---- */              \
    {                                                                                 \
        int kk0 = kp + bw0;                                                           \
        int kk1 = kk0 + 32;                                                           \
        const float* s0 = Wrow + ((kk0 < F_DIM) ? kk0 : 0);  /* clamp: A zeros cover */\
        const float* s1 = Wrow + ((kk1 < F_DIM) ? kk1 : 0);                           \
        uint32_t dst = bB + bdst0;                                                    \
        _Pragma("unroll")                                                             \
        for (int i = 0; i < 18; i++) {                                                \
            cpasync4(dst, s0);                                                        \
            cpasync4(dst + 128, s1);                                                  \
            dst += 16 * 256;                                                          \
            s0 += (size_t)16 * F_DIM;                                                 \
            s1 += (size_t)16 * F_DIM;                                                 \
        }                                                                             \
        if (bn0 < 12) { cpasync4(dst, s0); cpasync4(dst + 128, s1); }                 \
    }                                                                                 \
    kp += KT; vp += KT; if (vp >= AV) { vp -= AV; ap++; }                             \
} while (0)

    // prologue: produce stage 0
    PRODUCE(0); cp_commit();

    // consumer constants
    uint32_t arow0 = (uint32_t)(wm * 64 + lr);
    uint32_t swA   = 8u * (uint32_t)(lr & 1);
    uint32_t brow0 = (uint32_t)(wn * 40 + lr);
    uint32_t sBc   = (uint32_t)(lr & 1) << 2;

    float* dstp = g_part + (size_t)cta * B_DIM * P_DIM;
    int nfl = 0;
    int stage = 0;
    for (int c = 0; c < nt; c++) {
        cp_wait0();
        __syncthreads();
        if (c + 1 < nt) { PRODUCE(1 - stage); cp_commit(); }

        if (hasb && c == cf) {             // close pure-a0 segment
            flush_acc(acc, dstp, wm, wn, lr, lc, a0, nfl > 0); nfl++;
        }

        uint32_t aB = base_s + stage * STG_BYTES;
        uint32_t bB = aB + A_BYTES;

        #pragma unroll
        for (int g = 0; g < 4; g++) {
            uint32_t agr = (((uint32_t)(4 * g + lc)) ^ swA) * 8;
            uint32_t Alo[4][2], Ahi[4][2];
            {
                uint32_t aaddr = aB + arow0 * 128 + agr;
                #pragma unroll
                for (int m = 0; m < 4; m++) {
                    lds64(aaddr,        Alo[m][0], Alo[m][1]);
                    lds64(aaddr + 1024, Ahi[m][0], Ahi[m][1]);   // row +8
                    aaddr += 16 * 128;
                }
            }
            uint32_t bchunk = (((uint32_t)(g * 4 + lc)) ^ sBc) * 16;
            uint32_t baddr = bB + brow0 * 256 + bchunk;
            #pragma unroll
            for (int n = 0; n < 5; n++) {
                uint32_t bw[4];
                lds128(baddr, bw[0], bw[1], bw[2], bw[3]);
                baddr += 8 * 256;
                uint32_t b0 = cvt2h(__uint_as_float(bw[1]), __uint_as_float(bw[0]));
                uint32_t b1 = cvt2h(__uint_as_float(bw[3]), __uint_as_float(bw[2]));
                #pragma unroll
                for (int m = 0; m < 4; m++) {
                    mma_f16(acc[m][n][0], acc[m][n][1], acc[m][n][2], acc[m][n][3],
                            Alo[m][0], Ahi[m][0], Alo[m][1], Ahi[m][1], b0, b1);
                }
            }
        }

        if (hasb && mixed && c == cf) {    // mixed tile was premultiplied: scale 1
            flush_acc(acc, dstp, wm, wn, lr, lc, -1, true); nfl++;
        }
        stage ^= 1;
    }

    // final flush: remaining segment's scale
    flush_acc(acc, dstp, wm, wn, lr, lc, hasb ? a0 + 1 : a0, nfl > 0);
#undef PRODUCE
}

// ---------------- kernel 3a: split-K reduce phase 1 (148 -> 8) ----------------
__global__ void reduce1_kernel() {
    const int NG4 = B_DIM * P_DIM / 4;                    // 9600
    int g4 = blockIdx.x * blockDim.x + threadIdx.x;
    if (g4 >= NG4) return;
    int part = blockIdx.y;                                // 0..7
    int c0 = part * 18 + min(part, 4);                    // 148 = 4*19 + 4*18
    int cn = 18 + (part < 4 ? 1 : 0);
    const float4* base = reinterpret_cast<const float4*>(g_part) + (size_t)c0 * NG4 + g4;
    float4 s0 = make_float4(0.f, 0.f, 0.f, 0.f);
    float4 s1 = make_float4(0.f, 0.f, 0.f, 0.f);
    float4 s2 = make_float4(0.f, 0.f, 0.f, 0.f);
    float4 s3 = make_float4(0.f, 0.f, 0.f, 0.f);
    int c = 0;
    #pragma unroll
    for (; c + 4 <= 18; c += 4) {
        float4 v0 = base[(size_t)(c + 0) * NG4];
        float4 v1 = base[(size_t)(c + 1) * NG4];
        float4 v2 = base[(size_t)(c + 2) * NG4];
        float4 v3 = base[(size_t)(c + 3) * NG4];
        s0.x += v0.x; s0.y += v0.y; s0.z += v0.z; s0.w += v0.w;
        s1.x += v1.x; s1.y += v1.y; s1.z += v1.z; s1.w += v1.w;
        s2.x += v2.x; s2.y += v2.y; s2.z += v2.z; s2.w += v2.w;
        s3.x += v3.x; s3.y += v3.y; s3.z += v3.z; s3.w += v3.w;
    }
    for (; c < cn; c++) {
        float4 v0 = base[(size_t)c * NG4];
        s0.x += v0.x; s0.y += v0.y; s0.z += v0.z; s0.w += v0.w;
    }
    float4 o;
    o.x = (s0.x + s1.x) + (s2.x + s3.x);
    o.y = (s0.y + s1.y) + (s2.y + s3.y);
    o.z = (s0.z + s1.z) + (s2.z + s3.z);
    o.w = (s0.w + s1.w) + (s2.w + s3.w);
    reinterpret_cast<float4*>(g_R4)[part * NG4 + g4] = o;
}

// ---------------- kernel 3b: reduce phase 2 + bias + relu ----------------
__global__ void reduce2_kernel(const float* __restrict__ b1) {
    const int NG4 = B_DIM * P_DIM / 4;
    int g4 = blockIdx.x * blockDim.x + threadIdx.x;
    if (g4 >= NG4) return;
    const float4* R = reinterpret_cast<const float4*>(g_R4);
    float sx = 0.f, sy = 0.f, sz = 0.f, sw = 0.f;
    #pragma unroll
    for (int p = 0; p < RPARTS; p++) {
        float4 v = R[p * NG4 + g4];
        sx += v.x; sy += v.y; sz += v.z; sw += v.w;
    }
    int col = (g4 * 4) % P_DIM;
    float4 o;
    o.x = fmaxf(sx + __ldg(b1 + col + 0), 0.f);
    o.y = fmaxf(sy + __ldg(b1 + col + 1), 0.f);
    o.z = fmaxf(sz + __ldg(b1 + col + 2), 0.f);
    o.w = fmaxf(sw + __ldg(b1 + col + 3), 0.f);
    reinterpret_cast<float4*>(g_H)[g4] = o;
}

// ---------------- kernel 4: output layer ----------------
__global__ void out_kernel(const float* __restrict__ W2, const float* __restrict__ b2,
                           float* __restrict__ out) {
    __shared__ float w[P_DIM];
    int o = blockIdx.x;
    for (int i = threadIdx.x; i < P_DIM; i += blockDim.x) w[i] = W2[o * P_DIM + i];
    __syncthreads();
    int b = threadIdx.x;
    if (b < B_DIM) {
        const float* h = g_H + b * P_DIM;
        float s = __ldg(b2 + o);
        #pragma unroll 4
        for (int p = 0; p < P_DIM; p++) s += h[p] * w[p];
        out[b * P_DIM + o] = fmaxf(s, 0.0f);
    }
}

// ---------------- launch ----------------
extern "C" void kernel_launch(void* const* d_in, const int* in_sizes, int n_in,
                              void* d_out, int out_size) {
    const float* ax = (const float*)d_in[0];
    const float* vx = (const float*)d_in[1];
    const float* tx = (const float*)d_in[2];
    const float* Wa = (const float*)d_in[3];
    const float* ba = (const float*)d_in[4];
    const float* Wv = (const float*)d_in[5];
    const float* bv = (const float*)d_in[6];
    const float* Wt = (const float*)d_in[7];
    const float* bt = (const float*)d_in[8];
    const float* W1 = (const float*)d_in[9];
    const float* b1 = (const float*)d_in[10];
    const float* W2 = (const float*)d_in[11];
    const float* b2 = (const float*)d_in[12];
    float* out = (float*)d_out;

    cudaFuncSetAttribute(main_kernel, cudaFuncAttributeMaxDynamicSharedMemorySize, DYN_SMEM);

    prep_kernel<<<B_DIM, 384>>>(ax, vx, tx, Wa, ba, Wv, bv, Wt, bt);
    dummy_kernel<<<1, 32>>>();   // keep main_kernel as launch #4 for the ncu window
    dummy_kernel<<<1, 32>>>();
    main_kernel<<<NCTA, NTHR, DYN_SMEM>>>(W1);
    reduce1_kernel<<<dim3((B_DIM * P_DIM / 4 + 255) / 256, RPARTS), 256>>>();
    reduce2_kernel<<<(B_DIM * P_DIM / 4 + 255) / 256, 256>>>(b1);
    out_kernel<<<P_DIM, 128>>>(W2, b2, out);
}

// round 17
// speedup vs baseline: 1.1402x; 1.1402x over previous
#include <cuda_runtime.h>
#include <cuda_fp16.h>
#include <cstdint>

// ---------------- problem constants ----------------
#define B_DIM 128
#define H_DIM 101            // 100 hidden + leading 1
#define AV 10201             // 101*101
#define F_DIM 1030301        // 101^3
#define P_DIM 300
#define KT 64                // K per pipeline tile
#define TILES 16099          // ceil(F_DIM / 64)
#define NCTA 148             // K-split
#define NTHR 512
#define A_BYTES (128 * 128)           // A tile: 128 rows x 128B (fp16, k64, slot-ordered chunks)
#define B_BYTES (320 * 256)           // B tile: 320 rows x 256B (fp32; rows>=300 junk)
#define STG_BYTES (A_BYTES + B_BYTES) // 98304
#define DYN_SMEM (2 * STG_BYTES)      // 196608
#define RPARTS 8

// ---------------- device scratch (no allocs allowed) ----------------
__device__ float g_HA[B_DIM * H_DIM];                            // audio hidden (with leading 1)
__device__ float g_VT[B_DIM * AV];                               // VT = _v (x) _t, L2-resident
__device__ __align__(16) float g_part[(size_t)NCTA * B_DIM * P_DIM];
__device__ __align__(16) float g_R4[RPARTS * B_DIM * P_DIM];
__device__ __align__(16) float g_H[B_DIM * P_DIM];

// ---------------- helpers ----------------
__device__ __forceinline__ uint32_t smem_u32(const void* p) {
    uint32_t a;
    asm("{ .reg .u64 t; cvta.to.shared.u64 t, %1; cvt.u32.u64 %0, t; }" : "=r"(a) : "l"(p));
    return a;
}
// pack two fp32 -> f16x2 (first arg -> upper half, second -> lower half)
__device__ __forceinline__ uint32_t cvt2h(float hi, float lo) {
    uint32_t r;
    asm("cvt.rn.f16x2.f32 %0, %1, %2;" : "=r"(r) : "f"(hi), "f"(lo));
    return r;
}
__device__ __forceinline__ void sts128(uint32_t a, uint32_t v0, uint32_t v1,
                                       uint32_t v2, uint32_t v3) {
    asm volatile("st.shared.v4.b32 [%0], {%1,%2,%3,%4};"
                 :: "r"(a), "r"(v0), "r"(v1), "r"(v2), "r"(v3) : "memory");
}
__device__ __forceinline__ void lds128(uint32_t a, uint32_t& v0, uint32_t& v1,
                                       uint32_t& v2, uint32_t& v3) {
    asm volatile("ld.shared.v4.b32 {%0,%1,%2,%3}, [%4];"
                 : "=r"(v0), "=r"(v1), "=r"(v2), "=r"(v3) : "r"(a));
}
// ldmatrix x4: 4 m8k8 fp16 matrices, reg i <- address group i
__device__ __forceinline__ void ldsm4(uint32_t* r, uint32_t addr) {
    asm volatile("ldmatrix.sync.aligned.m8n8.x4.shared.b16 {%0,%1,%2,%3}, [%4];"
                 : "=r"(r[0]), "=r"(r[1]), "=r"(r[2]), "=r"(r[3]) : "r"(addr));
}
__device__ __forceinline__ void cpasync4(uint32_t dst, const void* src) {
    asm volatile("cp.async.ca.shared.global [%0], [%1], 4;" :: "r"(dst), "l"(src) : "memory");
}
__device__ __forceinline__ void cp_commit() {
    asm volatile("cp.async.commit_group;" ::: "memory");
}
__device__ __forceinline__ void cp_wait0() {
    asm volatile("cp.async.wait_group 0;" ::: "memory");
}
// fp16 MMA, m16n8k16, fp32 accumulate
__device__ __forceinline__ void mma_f16(float& d0, float& d1, float& d2, float& d3,
                                        uint32_t a0, uint32_t a1, uint32_t a2, uint32_t a3,
                                        uint32_t b0, uint32_t b1) {
    asm volatile("mma.sync.aligned.m16n8k16.row.col.f32.f16.f16.f32 "
                 "{%0,%1,%2,%3}, {%4,%5,%6,%7}, {%8,%9}, {%0,%1,%2,%3};"
                 : "+f"(d0), "+f"(d1), "+f"(d2), "+f"(d3)
                 : "r"(a0), "r"(a1), "r"(a2), "r"(a3), "r"(b0), "r"(b1));
}

// ---------------- kernel 1: fused encoders + VT precompute ----------------
__global__ void prep_kernel(const float* __restrict__ ax, const float* __restrict__ vx,
                            const float* __restrict__ tx,
                            const float* __restrict__ Wa, const float* __restrict__ ba,
                            const float* __restrict__ Wv, const float* __restrict__ bv,
                            const float* __restrict__ Wt, const float* __restrict__ bt) {
    __shared__ float xs[900];
    __shared__ float hv[H_DIM], ht[H_DIM];
    int b = blockIdx.x;
    int tid = threadIdx.x;   // 384 threads
    for (int i = tid; i < 900; i += 384) {
        const float* x = (i < 300) ? ax : (i < 600) ? vx : tx;
        xs[i] = x[b * 300 + (i % 300)];
    }
    __syncthreads();
    if (tid < 300) {
        int m = tid / 100, jj = tid - m * 100;
        const float* W    = (m == 0) ? Wa : (m == 1) ? Wv : Wt;
        const float* bias = (m == 0) ? ba : (m == 1) ? bv : bt;
        const float* w = W + jj * 300;
        const float* xp = xs + m * 300;
        float s = 0.0f;
        #pragma unroll 4
        for (int p = 0; p < 300; p++) s += xp[p] * __ldg(w + p);
        s += __ldg(bias + jj);
        if (m == 0) g_HA[b * H_DIM + 1 + jj] = s;
        else if (m == 1) hv[1 + jj] = s;
        else ht[1 + jj] = s;
    }
    if (tid == 300) g_HA[b * H_DIM] = 1.0f;
    if (tid == 301) hv[0] = 1.0f;
    if (tid == 302) ht[0] = 1.0f;
    __syncthreads();
    for (int i = tid; i < AV; i += 384) {
        int v = i / 101, t = i - v * 101;
        g_VT[b * AV + i] = hv[v] * ht[t];
    }
}

// ---------------- dummy kernels: keep main_kernel as launch #4 for the ncu window ----------------
__global__ void dummy_kernel() {}

// ---------------- kernel 2: main split-K GEMM (512 thr, fp16 m16n8k16, KT=64) ----------------
// Grid 148 (K-split). 16 warps, warp grid 2M x 8N, warp tile 64 x 40. acc = 80 regs.
// A smem: fp16, row 128B = 8 chunks of 16B. Logical chunk L = 2g+h (g=0..3; h=0 lo-slots,
//   h=1 hi-slots); physical chunk = L ^ (row&7). Chunk content (positions 0..7):
//   h=0: phys k 16g+{0,1,4,5,8,9,12,13}; h=1: 16g+{2,3,6,7,10,11,14,15}.
//   After ldmatrix, lane (lr,lc) reg pair = positions 2lc,2lc+1 -> slots (2lc,2lc+1) for h=0
//   and (2lc+8,2lc+9) for h=1 — exactly matching the B packing below. Conflict-free both sides.
// B smem: fp32, row 256B, k contiguous, 16B chunk ^ ((row&1)*4) (proven layout).
__global__ void __launch_bounds__(NTHR, 1) main_kernel(const float* __restrict__ W1) {
    extern __shared__ char dyn[];
    uint32_t base_s = smem_u32(dyn);

    int tid = threadIdx.x, wid = tid >> 5, lane = tid & 31;
    int cta = blockIdx.x;
    int wm = wid & 1;          // M half: rows wm*64
    int wn = wid >> 1;         // N block: cols wn*40 (0..7)
    int lr = lane >> 2;        // 0..7
    int lc = lane & 3;         // 0..3

    // contiguous K-tile range for this CTA
    int q = TILES / NCTA;                  // 108
    int r = TILES - q * NCTA;              // 115
    int t0 = cta * q + min(cta, r);
    int nt = q + (cta < r ? 1 : 0);

    // ---- producer rolling state ----
    int kp = t0 * KT;
    int ap = kp / AV;
    int vp = kp - ap * AV;

    // A producer: row = tid>>2, gp = tid&3 (one k16 group = two 16B chunks)
    int arow = tid >> 2;
    int gp   = tid & 3;
    uint32_t rk = (uint32_t)(arow & 7);
    // B producer: warp w covers rows bn0+16i; thread covers words bw0, bw0+32
    int bn0 = tid >> 5;
    int bw0 = tid & 31;
    const float* Wrow = W1 + (size_t)bn0 * F_DIM;
    uint32_t bdst0 = (uint32_t)(bn0 * 256 + (((bw0 >> 2) ^ ((bn0 & 1) * 4)) * 16) + (bw0 & 3) * 4);

    float acc[4][5][4];
    #pragma unroll
    for (int m = 0; m < 4; m++)
        #pragma unroll
        for (int n = 0; n < 5; n++)
            #pragma unroll
            for (int e = 0; e < 4; e++) acc[m][n][e] = 0.0f;

#define PRODUCE(S) do {                                                               \
    uint32_t aB = base_s + (S) * STG_BYTES;                                           \
    uint32_t bB = aB + A_BYTES;                                                       \
    /* ---- A tile: one k16 group per thread, slot-ordered 16B chunks ---- */         \
    uint32_t abase = aB + arow * 128;                                                 \
    float f[16];                                                                      \
    if (vp <= AV - KT && kp + KT <= F_DIM) {  /* fast: 'a' constant over tile */      \
        float ha = g_HA[arow * H_DIM + ap];                                           \
        const float* vrow = g_VT + (size_t)arow * AV + vp + 16 * gp;                  \
        _Pragma("unroll")                                                             \
        for (int j = 0; j < 16; j++) f[j] = ha * vrow[j];                             \
    } else {                                  /* slow: per-element, division-free */  \
        _Pragma("unroll")                                                             \
        for (int j = 0; j < 16; j++) {                                                \
            int off = 16 * gp + j;                                                    \
            int k = kp + off;                                                         \
            float val = 0.0f;                                                         \
            if (k < F_DIM) {                                                          \
                int vv = vp + off;                                                    \
                int wrap = (vv >= AV);                                                \
                int a = ap + wrap;                                                    \
                int vt = vv - (wrap ? AV : 0);                                        \
                val = g_HA[arow * H_DIM + a] * g_VT[(size_t)arow * AV + vt];          \
            }                                                                         \
            f[j] = val;                                                               \
        }                                                                             \
    }                                                                                 \
    sts128(abase + (((uint32_t)(2 * gp + 0) ^ rk) * 16),                              \
           cvt2h(f[1], f[0]), cvt2h(f[5], f[4]), cvt2h(f[9], f[8]), cvt2h(f[13], f[12])); \
    sts128(abase + (((uint32_t)(2 * gp + 1) ^ rk) * 16),                              \
           cvt2h(f[3], f[2]), cvt2h(f[7], f[6]), cvt2h(f[11], f[10]), cvt2h(f[15], f[14])); \
    /* ---- B tile: 300 rows x 64 words (fp32), rolling pointers ---- */              \
    {                                                                                 \
        int kk0 = kp + bw0;                                                           \
        int kk1 = kk0 + 32;                                                           \
        const float* s0 = Wrow + ((kk0 < F_DIM) ? kk0 : 0);  /* clamp: A zeros cover */\
        const float* s1 = Wrow + ((kk1 < F_DIM) ? kk1 : 0);                           \
        uint32_t dst = bB + bdst0;                                                    \
        _Pragma("unroll")                                                             \
        for (int i = 0; i < 18; i++) {                                                \
            cpasync4(dst, s0);                                                        \
            cpasync4(dst + 128, s1);                                                  \
            dst += 16 * 256;                                                          \
            s0 += (size_t)16 * F_DIM;                                                 \
            s1 += (size_t)16 * F_DIM;                                                 \
        }                                                                             \
        if (bn0 < 12) { cpasync4(dst, s0); cpasync4(dst + 128, s1); }                 \
    }                                                                                 \
    kp += KT; vp += KT; if (vp >= AV) { vp -= AV; ap++; }                             \
} while (0)

    // prologue: produce stage 0
    PRODUCE(0); cp_commit();

    // consumer constants
    uint32_t rowoff = (uint32_t)((lane & 7) + 8 * ((lane >> 3) & 1));  // 0..15
    uint32_t hsel   = (uint32_t)(lane >> 4);                           // chunk half
    uint32_t lk     = (uint32_t)(lane & 7);
    uint32_t abase0 = ((uint32_t)(wm * 64) + rowoff) * 128;
    uint32_t brow0  = (uint32_t)(wn * 40 + lr);
    uint32_t sBc    = (uint32_t)(lr & 1) << 2;

    int stage = 0;
    for (int c = 0; c < nt; c++) {
        cp_wait0();
        __syncthreads();
        if (c + 1 < nt) { PRODUCE(1 - stage); cp_commit(); }

        uint32_t aB = base_s + stage * STG_BYTES;
        uint32_t bB = aB + A_BYTES;

        #pragma unroll
        for (int g = 0; g < 4; g++) {
            // A fragments: 4 ldmatrix.x4 (one per m-tile)
            uint32_t A4[4][4];
            {
                uint32_t choff = (((uint32_t)(2 * g) + hsel) ^ lk) * 16;
                uint32_t aaddr = aB + abase0 + choff;
                #pragma unroll
                for (int m = 0; m < 4; m++) {
                    ldsm4(A4[m], aaddr);
                    aaddr += 16 * 128;
                }
            }
            // B: batch all 5 lds128 (independent, latency overlapped)
            uint32_t bwv[5][4];
            {
                uint32_t bchunk = (((uint32_t)(g * 4 + lc)) ^ sBc) * 16;
                uint32_t baddr = bB + brow0 * 256 + bchunk;
                #pragma unroll
                for (int n = 0; n < 5; n++) {
                    lds128(baddr, bwv[n][0], bwv[n][1], bwv[n][2], bwv[n][3]);
                    baddr += 8 * 256;
                }
            }
            #pragma unroll
            for (int n = 0; n < 5; n++) {
                uint32_t b0 = cvt2h(__uint_as_float(bwv[n][1]), __uint_as_float(bwv[n][0]));
                uint32_t b1 = cvt2h(__uint_as_float(bwv[n][3]), __uint_as_float(bwv[n][2]));
                #pragma unroll
                for (int m = 0; m < 4; m++) {
                    mma_f16(acc[m][n][0], acc[m][n][1], acc[m][n][2], acc[m][n][3],
                            A4[m][0], A4[m][1], A4[m][2], A4[m][3], b0, b1);
                }
            }
        }
        stage ^= 1;
    }

    // ---- epilogue: deterministic per-CTA partials ----
    float* dst = g_part + (size_t)cta * B_DIM * P_DIM;
    #pragma unroll
    for (int m = 0; m < 4; m++) {
        int row = wm * 64 + m * 16 + lr;
        #pragma unroll
        for (int n = 0; n < 5; n++) {
            int col = wn * 40 + n * 8 + lc * 2;
            if (col < 300) {
                float2 v0 = make_float2(acc[m][n][0], acc[m][n][1]);
                float2 v1 = make_float2(acc[m][n][2], acc[m][n][3]);
                *reinterpret_cast<float2*>(dst + (size_t)row * P_DIM + col) = v0;
                *reinterpret_cast<float2*>(dst + (size_t)(row + 8) * P_DIM + col) = v1;
            }
        }
    }
#undef PRODUCE
}

// ---------------- kernel 3a: split-K reduce phase 1 (148 -> 8) ----------------
__global__ void reduce1_kernel() {
    const int NG4 = B_DIM * P_DIM / 4;                    // 9600
    int g4 = blockIdx.x * blockDim.x + threadIdx.x;
    if (g4 >= NG4) return;
    int part = blockIdx.y;                                // 0..7
    int c0 = part * 18 + min(part, 4);                    // 148 = 4*19 + 4*18
    int cn = 18 + (part < 4 ? 1 : 0);
    const float4* base = reinterpret_cast<const float4*>(g_part) + (size_t)c0 * NG4 + g4;
    float4 s0 = make_float4(0.f, 0.f, 0.f, 0.f);
    float4 s1 = make_float4(0.f, 0.f, 0.f, 0.f);
    float4 s2 = make_float4(0.f, 0.f, 0.f, 0.f);
    float4 s3 = make_float4(0.f, 0.f, 0.f, 0.f);
    int c = 0;
    #pragma unroll
    for (; c + 4 <= 18; c += 4) {
        float4 v0 = base[(size_t)(c + 0) * NG4];
        float4 v1 = base[(size_t)(c + 1) * NG4];
        float4 v2 = base[(size_t)(c + 2) * NG4];
        float4 v3 = base[(size_t)(c + 3) * NG4];
        s0.x += v0.x; s0.y += v0.y; s0.z += v0.z; s0.w += v0.w;
        s1.x += v1.x; s1.y += v1.y; s1.z += v1.z; s1.w += v1.w;
        s2.x += v2.x; s2.y += v2.y; s2.z += v2.z; s2.w += v2.w;
        s3.x += v3.x; s3.y += v3.y; s3.z += v3.z; s3.w += v3.w;
    }
    for (; c < cn; c++) {
        float4 v0 = base[(size_t)c * NG4];
        s0.x += v0.x; s0.y += v0.y; s0.z += v0.z; s0.w += v0.w;
    }
    float4 o;
    o.x = (s0.x + s1.x) + (s2.x + s3.x);
    o.y = (s0.y + s1.y) + (s2.y + s3.y);
    o.z = (s0.z + s1.z) + (s2.z + s3.z);
    o.w = (s0.w + s1.w) + (s2.w + s3.w);
    reinterpret_cast<float4*>(g_R4)[part * NG4 + g4] = o;
}

// ---------------- kernel 3b: reduce phase 2 + bias + relu ----------------
__global__ void reduce2_kernel(const float* __restrict__ b1) {
    const int NG4 = B_DIM * P_DIM / 4;
    int g4 = blockIdx.x * blockDim.x + threadIdx.x;
    if (g4 >= NG4) return;
    const float4* R = reinterpret_cast<const float4*>(g_R4);
    float sx = 0.f, sy = 0.f, sz = 0.f, sw = 0.f;
    #pragma unroll
    for (int p = 0; p < RPARTS; p++) {
        float4 v = R[p * NG4 + g4];
        sx += v.x; sy += v.y; sz += v.z; sw += v.w;
    }
    int col = (g4 * 4) % P_DIM;
    float4 o;
    o.x = fmaxf(sx + __ldg(b1 + col + 0), 0.f);
    o.y = fmaxf(sy + __ldg(b1 + col + 1), 0.f);
    o.z = fmaxf(sz + __ldg(b1 + col + 2), 0.f);
    o.w = fmaxf(sw + __ldg(b1 + col + 3), 0.f);
    reinterpret_cast<float4*>(g_H)[g4] = o;
}

// ---------------- kernel 4: output layer ----------------
__global__ void out_kernel(const float* __restrict__ W2, const float* __restrict__ b2,
                           float* __restrict__ out) {
    __shared__ float w[P_DIM];
    int o = blockIdx.x;
    for (int i = threadIdx.x; i < P_DIM; i += blockDim.x) w[i] = W2[o * P_DIM + i];
    __syncthreads();
    int b = threadIdx.x;
    if (b < B_DIM) {
        const float* h = g_H + b * P_DIM;
        float s = __ldg(b2 + o);
        #pragma unroll 4
        for (int p = 0; p < P_DIM; p++) s += h[p] * w[p];
        out[b * P_DIM + o] = fmaxf(s, 0.0f);
    }
}

// ---------------- launch ----------------
extern "C" void kernel_launch(void* const* d_in, const int* in_sizes, int n_in,
                              void* d_out, int out_size) {
    const float* ax = (const float*)d_in[0];
    const float* vx = (const float*)d_in[1];
    const float* tx = (const float*)d_in[2];
    const float* Wa = (const float*)d_in[3];
    const float* ba = (const float*)d_in[4];
    const float* Wv = (const float*)d_in[5];
    const float* bv = (const float*)d_in[6];
    const float* Wt = (const float*)d_in[7];
    const float* bt = (const float*)d_in[8];
    const float* W1 = (const float*)d_in[9];
    const float* b1 = (const float*)d_in[10];
    const float* W2 = (const float*)d_in[11];
    const float* b2 = (const float*)d_in[12];
    float* out = (float*)d_out;

    cudaFuncSetAttribute(main_kernel, cudaFuncAttributeMaxDynamicSharedMemorySize, DYN_SMEM);

    prep_kernel<<<B_DIM, 384>>>(ax, vx, tx, Wa, ba, Wv, bv, Wt, bt);
    dummy_kernel<<<1, 32>>>();   // keep main_kernel as launch #4 for the ncu window
    dummy_kernel<<<1, 32>>>();
    main_kernel<<<NCTA, NTHR, DYN_SMEM>>>(W1);
    reduce1_kernel<<<dim3((B_DIM * P_DIM / 4 + 255) / 256, RPARTS), 256>>>();
    reduce2_kernel<<<(B_DIM * P_DIM / 4 + 255) / 256, 256>>>(b1);
    out_kernel<<<P_DIM, 128>>>(W2, b2, out);
}